// round 12
// baseline (speedup 1.0000x reference)
#include <cuda_runtime.h>
#include <cuda_bf16.h>
#include <cuda_fp16.h>
#include <cstdint>

// BatchSRU: L=2048, B=8, D=128, NB=16, fp32. HMMA mma.sync bf16, 3-combo fp32
// emulation. Pass1: transpose+split x -> g_xhi/g_xlo [b][nb][t][k].
// Pass2: per-(b,nb) CTA, 384 threads, NT=32:
//   warps 4-11: GEMM U[h][t]=sum_k W[k][h]x[t][k]; Whi mtiles mi=0,1 hoisted to
//        regs (64), mi=2 + Wlo via ldsm. Prefetch x(i+1) LDG in phase A,
//        STS in phase B.
//   warps 0-3:  scan tile i-1 (regs + xv from XB SMEM) CONCURRENT with GEMM(i);
//        phase B drains U(i) to regs. h written coalesced to g_hT.
// Pass3: untranspose g_hT -> out(l,b,d,nb).

#define L_SEQ 2048
#define BATCH 8
#define DIM   128
#define NBI   16
#define NT    32
#define NTILES 64

__device__ __nv_bfloat16 g_xhi[BATCH * NBI * L_SEQ * DIM];
__device__ __nv_bfloat16 g_xlo[BATCH * NBI * L_SEQ * DIM];
__device__ float         g_hT [BATCH * NBI * L_SEQ * DIM];

// SMEM: startup Whi(rearranged) [0,96K): hoistable mtiles [0,64K) + resident
// mi=2 mtiles [64K,96K). Wlo full [96K,192K). After hoist, [0,64K) overlaid:
#define OFF_XB   0           // 2 bufs x 16384 (hi 8192 + lo 8192)
#define OFF_UX   32768       // fp32 [32][128] = 16384
#define OFF_UF   49152       // fp16 [32][128] = 8192
#define OFF_UR   57344       // fp16 [32][128] = 8192
#define OFF_WH2  65536       // resident Whi mi=2: 128 rows x 256 B = 32768
#define OFF_WLO  98304       // full Wlo: 384 rows x 256 B = 98304
#define SMEM_MAIN 196608

__device__ __forceinline__ uint32_t smem_u32(const void* p) {
    uint32_t a;
    asm("{ .reg .u64 t; cvta.to.shared.u64 t, %1; cvt.u32.u64 %0, t; }" : "=r"(a) : "l"(p));
    return a;
}
__device__ __forceinline__ void ldsm_x4(uint32_t* r, uint32_t addr) {
    asm volatile("ldmatrix.sync.aligned.m8n8.x4.shared.b16 {%0,%1,%2,%3}, [%4];"
                 : "=r"(r[0]), "=r"(r[1]), "=r"(r[2]), "=r"(r[3]) : "r"(addr));
}
__device__ __forceinline__ void ldsm_x2(uint32_t* r, uint32_t addr) {
    asm volatile("ldmatrix.sync.aligned.m8n8.x2.shared.b16 {%0,%1}, [%2];"
                 : "=r"(r[0]), "=r"(r[1]) : "r"(addr));
}
__device__ __forceinline__ void mma_bf16(float* d, const uint32_t* a, const uint32_t* b) {
    asm volatile("mma.sync.aligned.m16n8k16.row.col.f32.bf16.bf16.f32 "
                 "{%0,%1,%2,%3}, {%4,%5,%6,%7}, {%8,%9}, {%0,%1,%2,%3};"
                 : "+f"(d[0]), "+f"(d[1]), "+f"(d[2]), "+f"(d[3])
                 : "r"(a[0]), "r"(a[1]), "r"(a[2]), "r"(a[3]), "r"(b[0]), "r"(b[1]));
}
__device__ __forceinline__ float sigf(float z) {
    return __fdividef(1.0f, 1.0f + __expf(-z));
}

// ============ Pass 1: transpose + hi/lo split ============
#define TP_T 4
__global__ void __launch_bounds__(256) transpose_x(const float* __restrict__ x) {
    __shared__ float sm[TP_T * 16 * 129];
    const int bx = blockIdx.x;
    const int t0 = (bx >> 3) * TP_T;
    const int b  = bx & 7;
    #pragma unroll 4
    for (int i = 0; i < 32; i++) {
        int idx  = i * 256 + threadIdx.x;
        int tloc = idx >> 11;
        int rem  = idx & 2047;                  // k*16 + nb
        float v = x[((size_t)(t0 + tloc) * BATCH + b) * 2048 + rem];
        sm[(tloc * 16 + (rem & 15)) * 129 + (rem >> 4)] = v;
    }
    __syncthreads();
    #pragma unroll 4
    for (int i = 0; i < 32; i++) {
        int idx = i * 256 + threadIdx.x;
        int k = idx & 127;
        int chunk = idx >> 7;                   // nb*4 + tloc
        int nb = chunk >> 2, tloc = chunk & 3;
        float v = sm[(tloc * 16 + nb) * 129 + k];
        __nv_bfloat16 hi = __float2bfloat16(v);
        __nv_bfloat16 lo = __float2bfloat16(v - __bfloat162float(hi));
        size_t o = ((size_t)(b * NBI + nb) * L_SEQ + t0 + tloc) * DIM + k;
        g_xhi[o] = hi;
        g_xlo[o] = lo;
    }
}

// ============ Pass 3: untranspose h ============
__global__ void __launch_bounds__(256) untranspose_h(float* __restrict__ out) {
    __shared__ float sm[TP_T * 16 * 129];
    const int bx = blockIdx.x;
    const int t0 = (bx >> 3) * TP_T;
    const int b  = bx & 7;
    #pragma unroll 4
    for (int i = 0; i < 32; i++) {
        int idx = i * 256 + threadIdx.x;
        int k = idx & 127;
        int chunk = idx >> 7;
        int nb = chunk >> 2, tloc = chunk & 3;
        sm[(tloc * 16 + nb) * 129 + k] =
            g_hT[((size_t)(b * NBI + nb) * L_SEQ + t0 + tloc) * DIM + k];
    }
    __syncthreads();
    #pragma unroll 4
    for (int i = 0; i < 32; i++) {
        int idx  = i * 256 + threadIdx.x;
        int tloc = idx >> 11;
        int rem  = idx & 2047;
        out[((size_t)(t0 + tloc) * BATCH + b) * 2048 + rem] =
            sm[(tloc * 16 + (rem & 15)) * 129 + (rem >> 4)];
    }
}

// ============ Pass 2: main (384 threads) ============
__global__ void __launch_bounds__(384, 1) sru_main(
    const float* __restrict__ W, const float* __restrict__ bias)
{
    extern __shared__ char sm[];
    const uint32_t sb = smem_u32(sm);
    const int tid  = threadIdx.x;
    const int lane = tid & 31;
    const int wid  = tid >> 5;
    const int bx = blockIdx.x, nb = bx & 15;
    const bool is_scan = (tid < 128);

    // GEMM lane constants
    const int a_tile    = lane >> 3;
    const int a_row_add = (lane & 7) + ((a_tile & 1) << 3);
    const int a_chalf   = a_tile >> 1;
    const int b_row     = lane & 7;
    const int b_chalf   = (lane >> 3) & 1;
    const int g  = lane >> 2;
    const int tg = lane & 3;
    const int wg = wid - 4;                      // GEMM warp group 0..7

    // ---- startup: stage W (Whi rearranged, Wlo full) — thread owns column h=tid
    {
        const float* Wp = W + (size_t)nb * (DIM * 3 * DIM);
        const int h   = tid;
        const int mt  = h >> 4;
        const int wgh = mt / 3;
        const int mi  = mt - wgh * 3;
        const uint32_t hb = (mi < 2) ? (uint32_t)((wgh * 32 + mi * 16 + (h & 15)) * 256)
                                     : (uint32_t)(OFF_WH2 + (wgh * 16 + (h & 15)) * 256);
        const uint32_t lb = (uint32_t)(OFF_WLO + h * 256);
        #pragma unroll 4
        for (int k = 0; k < 128; k++) {
            float v = Wp[k * 384 + h];
            __nv_bfloat16 hi = __float2bfloat16(v);
            __nv_bfloat16 lo = __float2bfloat16(v - __bfloat162float(hi));
            uint32_t sw = (uint32_t)((((k >> 3) ^ (h & 15)) << 4) + ((k & 7) * 2));
            *(__nv_bfloat16*)(sm + hb + sw) = hi;
            *(__nv_bfloat16*)(sm + lb + sw) = lo;
        }
    }
    __syncthreads();

    // ---- GEMM warps: hoist Whi fragments for mi = 0,1 (64 regs)
    uint32_t Ahi2[2][8][4];
    if (!is_scan) {
        #pragma unroll
        for (int mi = 0; mi < 2; mi++) {
            int lrow = wg * 32 + mi * 16 + a_row_add;
            #pragma unroll
            for (int ks = 0; ks < 8; ks++) {
                uint32_t aa = sb + lrow * 256 + (((2 * ks + a_chalf) ^ (lrow & 15)) << 4);
                ldsm_x4(Ahi2[mi][ks], aa);
            }
        }
    }
    __syncthreads();                             // hoist region dead -> XB/U overlay

    // ---- stage XB(0) (GEMM threads: s = 0..255, 2 chunk-pairs each)
    if (!is_scan) {
        int s = tid - 128, t = s >> 3, q = s & 7;
        size_t o = ((size_t)bx * L_SEQ + t) * DIM + q * 16;
        uint4 H0 = *(const uint4*)(g_xhi + o), H1 = *(const uint4*)(g_xhi + o + 8);
        uint4 L0 = *(const uint4*)(g_xlo + o), L1 = *(const uint4*)(g_xlo + o + 8);
        uint32_t base = OFF_XB + (uint32_t)t * 256;
        int cc = q * 2;
        *(uint4*)(sm + base + (((cc)     ^ (t & 15)) << 4)) = H0;
        *(uint4*)(sm + base + (((cc + 1) ^ (t & 15)) << 4)) = H1;
        *(uint4*)(sm + base + 8192 + (((cc)     ^ (t & 15)) << 4)) = L0;
        *(uint4*)(sm + base + 8192 + (((cc + 1) ^ (t & 15)) << 4)) = L1;
    }
    // ---- scan init
    const int j = tid;
    float bfv = 0.0f, brv = 0.0f;
    if (is_scan) {
        bfv = bias[nb * 256 + j];
        brv = bias[nb * 256 + 128 + j];
    }
    float c = 0.0f;
    float xt[NT];
    __half fh[NT], rh[NT];
    __syncthreads();

    for (int i = 0; i < NTILES; i++) {
        const int buf = i & 1;
        uint4 H0, H1, L0, L1;                    // GEMM-thread prefetch regs

        if (!is_scan) {
            // -- prefetch x(i+1)
            if (i + 1 < NTILES) {
                int s = tid - 128, t = s >> 3, q = s & 7;
                size_t o = ((size_t)bx * L_SEQ + (size_t)(i + 1) * NT + t) * DIM + q * 16;
                H0 = *(const uint4*)(g_xhi + o); H1 = *(const uint4*)(g_xhi + o + 8);
                L0 = *(const uint4*)(g_xlo + o); L1 = *(const uint4*)(g_xlo + o + 8);
            }
            // ---------- GEMM(i): 3 mtiles x 4 n8tiles, NT=32
            float D[3][4][4];
            #pragma unroll
            for (int mi = 0; mi < 3; mi++)
                #pragma unroll
                for (int nt = 0; nt < 4; nt++)
                    #pragma unroll
                    for (int e = 0; e < 4; e++) D[mi][nt][e] = 0.0f;

            const uint32_t xb = sb + OFF_XB + (uint32_t)buf * 16384;
            const int lrow2 = wg * 16 + a_row_add;           // resident Whi mi=2
            #pragma unroll
            for (int ks = 0; ks < 8; ks++) {
                uint32_t Bhi[4][2], Blo[4][2];
                #pragma unroll
                for (int nt = 0; nt < 4; nt++) {
                    int trow = nt * 8 + b_row;
                    uint32_t ba = xb + trow * 256 + (((2 * ks + b_chalf) ^ (trow & 15)) << 4);
                    ldsm_x2(Bhi[nt], ba);
                    ldsm_x2(Blo[nt], ba + 8192);
                }
                uint32_t Ahi_m2[4];
                {
                    uint32_t aa = sb + OFF_WH2 + lrow2 * 256 +
                                  (((2 * ks + a_chalf) ^ (lrow2 & 15)) << 4);
                    ldsm_x4(Ahi_m2, aa);
                }
                #pragma unroll
                for (int mi = 0; mi < 3; mi++) {
                    int row = (wg * 3 + mi) * 16 + a_row_add;
                    uint32_t aa = sb + OFF_WLO + row * 256 +
                                  (((2 * ks + a_chalf) ^ (row & 15)) << 4);
                    uint32_t Alo[4];
                    ldsm_x4(Alo, aa);
                    const uint32_t* Ah = (mi < 2) ? Ahi2[mi][ks] : Ahi_m2;
                    #pragma unroll
                    for (int nt = 0; nt < 4; nt++) {
                        mma_bf16(D[mi][nt], Ah,  Bhi[nt]);
                        mma_bf16(D[mi][nt], Alo, Bhi[nt]);
                        mma_bf16(D[mi][nt], Ah,  Blo[nt]);
                    }
                }
            }
            // -- store U(i)
            #pragma unroll
            for (int mi = 0; mi < 3; mi++) {
                int mt = wg * 3 + mi;
                int gate = mt >> 3;
                int h0 = (mt & 7) * 16 + g;
                #pragma unroll
                for (int nt = 0; nt < 4; nt++) {
                    int t0 = nt * 8 + tg * 2;
                    if (gate == 0) {
                        float* u = (float*)(sm + OFF_UX);
                        u[(t0)     * DIM + h0]     = D[mi][nt][0];
                        u[(t0 + 1) * DIM + h0]     = D[mi][nt][1];
                        u[(t0)     * DIM + h0 + 8] = D[mi][nt][2];
                        u[(t0 + 1) * DIM + h0 + 8] = D[mi][nt][3];
                    } else {
                        __half* u = (__half*)(sm + (gate == 1 ? OFF_UF : OFF_UR));
                        u[(t0)     * DIM + h0]     = __float2half_rn(D[mi][nt][0]);
                        u[(t0 + 1) * DIM + h0]     = __float2half_rn(D[mi][nt][1]);
                        u[(t0)     * DIM + h0 + 8] = __float2half_rn(D[mi][nt][2]);
                        u[(t0 + 1) * DIM + h0 + 8] = __float2half_rn(D[mi][nt][3]);
                    }
                }
            }
        } else if (i > 0) {
            // ---------- scan(i-1), concurrent with GEMM(i). xv from XB[(i-1)&1].
            const uint32_t xbb = OFF_XB + (uint32_t)((i - 1) & 1) * 16384;
            float* hp = g_hT + ((size_t)bx * L_SEQ + (size_t)(i - 1) * NT) * DIM + j;
            #pragma unroll
            for (int t = 0; t < NT; t++) {
                float fv = sigf(__half2float(fh[t]) + bfv);
                float rv = sigf(__half2float(rh[t]) + brv);
                c = fmaf(fv, c - xt[t], xt[t]);
                uint32_t xa = xbb + t * 256 + (((j >> 3) ^ (t & 15)) << 4) + ((j & 7) * 2);
                float xv = __bfloat162float(*(__nv_bfloat16*)(sm + xa)) +
                           __bfloat162float(*(__nv_bfloat16*)(sm + xa + 8192));
                hp[t * DIM] = fmaf(rv, c - xv, xv);
            }
        }
        __syncthreads();                         // U(i) visible; scan(i-1) done

        if (!is_scan) {
            // -- STS x(i+1) into buffer (i+1)&1
            if (i + 1 < NTILES) {
                int s = tid - 128, t = s >> 3, q = s & 7;
                uint32_t base = OFF_XB + (uint32_t)((i + 1) & 1) * 16384 + (uint32_t)t * 256;
                int cc = q * 2;
                *(uint4*)(sm + base + (((cc)     ^ (t & 15)) << 4)) = H0;
                *(uint4*)(sm + base + (((cc + 1) ^ (t & 15)) << 4)) = H1;
                *(uint4*)(sm + base + 8192 + (((cc)     ^ (t & 15)) << 4)) = L0;
                *(uint4*)(sm + base + 8192 + (((cc + 1) ^ (t & 15)) << 4)) = L1;
            }
        } else {
            // -- drain U(i) to registers
            const float*  ux = (const float*)(sm + OFF_UX);
            const __half* uf = (const __half*)(sm + OFF_UF);
            const __half* ur = (const __half*)(sm + OFF_UR);
            #pragma unroll
            for (int t = 0; t < NT; t++) {
                xt[t] = ux[t * DIM + j];
                fh[t] = uf[t * DIM + j];
                rh[t] = ur[t * DIM + j];
            }
        }
        __syncthreads();                         // U free; XB((i+1)&1) staged
    }

    // -- final scan(NTILES-1); XB[(NTILES-1)&1] still intact
    if (is_scan) {
        const uint32_t xbb = OFF_XB + (uint32_t)((NTILES - 1) & 1) * 16384;
        float* hp = g_hT + ((size_t)bx * L_SEQ + (size_t)(NTILES - 1) * NT) * DIM + j;
        #pragma unroll
        for (int t = 0; t < NT; t++) {
            float fv = sigf(__half2float(fh[t]) + bfv);
            float rv = sigf(__half2float(rh[t]) + brv);
            c = fmaf(fv, c - xt[t], xt[t]);
            uint32_t xa = xbb + t * 256 + (((j >> 3) ^ (t & 15)) << 4) + ((j & 7) * 2);
            float xv = __bfloat162float(*(__nv_bfloat16*)(sm + xa)) +
                       __bfloat162float(*(__nv_bfloat16*)(sm + xa + 8192));
            hp[t * DIM] = fmaf(rv, c - xv, xv);
        }
    }
}

extern "C" void kernel_launch(void* const* d_in, const int* in_sizes, int n_in,
                              void* d_out, int out_size) {
    const float* x  = (const float*)d_in[0];
    const float* W  = (const float*)d_in[1];
    const float* bi = (const float*)d_in[2];
    float* out = (float*)d_out;

    transpose_x<<<(L_SEQ / TP_T) * BATCH, 256>>>(x);
    cudaFuncSetAttribute(sru_main, cudaFuncAttributeMaxDynamicSharedMemorySize, SMEM_MAIN);
    sru_main<<<BATCH * NBI, 384, SMEM_MAIN>>>(W, bi);
    untranspose_h<<<(L_SEQ / TP_T) * BATCH, 256>>>(out);
}

// round 13
// speedup vs baseline: 1.1217x; 1.1217x over previous
#include <cuda_runtime.h>
#include <cuda_bf16.h>
#include <cuda_fp16.h>
#include <cstdint>

// BatchSRU: L=2048, B=8, D=128, NB=16, fp32.
// x_tilde: 3-combo bf16 hi/lo HMMA (full fp32 emulation).
// f,r gates: single fp16 HMMA (sigmoid absorbs the ~2e-4 error).
// Pass1: transpose x -> g_xhi/g_xlo (bf16 split) + g_xh (fp16).
// Pass2: per-(b,nb) CTA, 384 threads, NT=32 tiles:
//   warps 4-7:  gate-0 GEMM (2 mtiles, Bhi+Blo, 3 combos)
//   warps 8-11: f/r GEMM   (4 mtiles, Bf fp16, 1 combo)
//   warps 0-3:  scan tile i-1 (regs) concurrent with GEMM(i); drain U in B.
//   GEMM threads prefetch x(i+1) in phase A (LDG) and STS in phase B.
// Pass3: untranspose g_hT -> out.

#define L_SEQ 2048
#define BATCH 8
#define DIM   128
#define NBI   16
#define NT    32
#define NTILES 64

__device__ __nv_bfloat16 g_xhi[BATCH * NBI * L_SEQ * DIM];
__device__ __nv_bfloat16 g_xlo[BATCH * NBI * L_SEQ * DIM];
__device__ __half        g_xh [BATCH * NBI * L_SEQ * DIM];
__device__ float         g_hT [BATCH * NBI * L_SEQ * DIM];

// SMEM (no overlays): W resident 128K, XB 2x24K, U 32K = 208K
#define OFF_WXHI 0            // gate0 W hi: 128 rows x 256B
#define OFF_WXLO 32768        // gate0 W lo
#define OFF_WFR  65536        // f,r W fp16: 256 rows x 256B
#define OFF_XB   131072       // 2 bufs x 24576: [xhi 8192][xlo 8192][xh 8192]
#define OFF_UX   180224       // fp32 [32][128]
#define OFF_UF   196608       // fp16 [32][128]
#define OFF_UR   204800       // fp16 [32][128]
#define SMEM_MAIN 212992

__device__ __forceinline__ uint32_t smem_u32(const void* p) {
    uint32_t a;
    asm("{ .reg .u64 t; cvta.to.shared.u64 t, %1; cvt.u32.u64 %0, t; }" : "=r"(a) : "l"(p));
    return a;
}
__device__ __forceinline__ void ldsm_x4(uint32_t* r, uint32_t addr) {
    asm volatile("ldmatrix.sync.aligned.m8n8.x4.shared.b16 {%0,%1,%2,%3}, [%4];"
                 : "=r"(r[0]), "=r"(r[1]), "=r"(r[2]), "=r"(r[3]) : "r"(addr));
}
__device__ __forceinline__ void mma_bf16(float* d, const uint32_t* a, const uint32_t* b) {
    asm volatile("mma.sync.aligned.m16n8k16.row.col.f32.bf16.bf16.f32 "
                 "{%0,%1,%2,%3}, {%4,%5,%6,%7}, {%8,%9}, {%0,%1,%2,%3};"
                 : "+f"(d[0]), "+f"(d[1]), "+f"(d[2]), "+f"(d[3])
                 : "r"(a[0]), "r"(a[1]), "r"(a[2]), "r"(a[3]), "r"(b[0]), "r"(b[1]));
}
__device__ __forceinline__ void mma_f16(float* d, const uint32_t* a, const uint32_t* b) {
    asm volatile("mma.sync.aligned.m16n8k16.row.col.f32.f16.f16.f32 "
                 "{%0,%1,%2,%3}, {%4,%5,%6,%7}, {%8,%9}, {%0,%1,%2,%3};"
                 : "+f"(d[0]), "+f"(d[1]), "+f"(d[2]), "+f"(d[3])
                 : "r"(a[0]), "r"(a[1]), "r"(a[2]), "r"(a[3]), "r"(b[0]), "r"(b[1]));
}
__device__ __forceinline__ float sigf(float z) {
    return __fdividef(1.0f, 1.0f + __expf(-z));
}

// ============ Pass 1: transpose + bf16 split + fp16 copy ============
#define TP_T 4
__global__ void __launch_bounds__(256) transpose_x(const float* __restrict__ x) {
    __shared__ float sm[TP_T * 16 * 129];
    const int bx = blockIdx.x;
    const int t0 = (bx >> 3) * TP_T;
    const int b  = bx & 7;
    #pragma unroll 4
    for (int i = 0; i < 32; i++) {
        int idx  = i * 256 + threadIdx.x;
        int tloc = idx >> 11;
        int rem  = idx & 2047;                  // k*16 + nb
        float v = x[((size_t)(t0 + tloc) * BATCH + b) * 2048 + rem];
        sm[(tloc * 16 + (rem & 15)) * 129 + (rem >> 4)] = v;
    }
    __syncthreads();
    #pragma unroll 4
    for (int i = 0; i < 32; i++) {
        int idx = i * 256 + threadIdx.x;
        int k = idx & 127;
        int chunk = idx >> 7;                   // nb*4 + tloc
        int nb = chunk >> 2, tloc = chunk & 3;
        float v = sm[(tloc * 16 + nb) * 129 + k];
        __nv_bfloat16 hi = __float2bfloat16(v);
        __nv_bfloat16 lo = __float2bfloat16(v - __bfloat162float(hi));
        size_t o = ((size_t)(b * NBI + nb) * L_SEQ + t0 + tloc) * DIM + k;
        g_xhi[o] = hi;
        g_xlo[o] = lo;
        g_xh[o]  = __float2half(v);
    }
}

// ============ Pass 3: untranspose h ============
__global__ void __launch_bounds__(256) untranspose_h(float* __restrict__ out) {
    __shared__ float sm[TP_T * 16 * 129];
    const int bx = blockIdx.x;
    const int t0 = (bx >> 3) * TP_T;
    const int b  = bx & 7;
    #pragma unroll 4
    for (int i = 0; i < 32; i++) {
        int idx = i * 256 + threadIdx.x;
        int k = idx & 127;
        int chunk = idx >> 7;
        int nb = chunk >> 2, tloc = chunk & 3;
        sm[(tloc * 16 + nb) * 129 + k] =
            g_hT[((size_t)(b * NBI + nb) * L_SEQ + t0 + tloc) * DIM + k];
    }
    __syncthreads();
    #pragma unroll 4
    for (int i = 0; i < 32; i++) {
        int idx  = i * 256 + threadIdx.x;
        int tloc = idx >> 11;
        int rem  = idx & 2047;
        out[((size_t)(t0 + tloc) * BATCH + b) * 2048 + rem] =
            sm[(tloc * 16 + (rem & 15)) * 129 + (rem >> 4)];
    }
}

// ============ Pass 2: main (384 threads) ============
__global__ void __launch_bounds__(384, 1) sru_main(
    const float* __restrict__ W, const float* __restrict__ bias)
{
    extern __shared__ char sm[];
    const uint32_t sb = smem_u32(sm);
    const int tid  = threadIdx.x;
    const int lane = tid & 31;
    const int wid  = tid >> 5;
    const int bx = blockIdx.x, nb = bx & 15;
    const bool is_scan = (tid < 128);

    // ---- lane constants
    const int a_tile    = lane >> 3;
    const int a_row_add = (lane & 7) + ((a_tile & 1) << 3);
    const int a_chalf   = a_tile >> 1;
    const int g  = lane >> 2;
    const int tg = lane & 3;
    // B ldsm_x4 lane mapping (pair p covers ntiles 2p, 2p+1)
    const int bm    = lane >> 3;                // matrix id 0..3
    const int brow0 = ((bm >> 1) << 3) + (lane & 7);   // row within pair (0..15)
    const int bmbit = bm & 1;                   // k-chunk parity

    // ---- startup: stage W (thread owns column h = tid, 0..383)
    {
        const float* Wp = W + (size_t)nb * (DIM * 3 * DIM);
        const int h = tid;
        const uint32_t rowswz = (uint32_t)(h & 15);
        if (h < 128) {
            #pragma unroll 4
            for (int k = 0; k < 128; k++) {
                float v = Wp[k * 384 + h];
                __nv_bfloat16 hi = __float2bfloat16(v);
                __nv_bfloat16 lo = __float2bfloat16(v - __bfloat162float(hi));
                uint32_t sw = (uint32_t)((((k >> 3) ^ rowswz) << 4) + ((k & 7) * 2));
                *(__nv_bfloat16*)(sm + OFF_WXHI + h * 256 + sw) = hi;
                *(__nv_bfloat16*)(sm + OFF_WXLO + h * 256 + sw) = lo;
            }
        } else {
            const int row = h - 128;            // 0..255 in WFR
            #pragma unroll 4
            for (int k = 0; k < 128; k++) {
                float v = Wp[k * 384 + h];
                uint32_t sw = (uint32_t)((((k >> 3) ^ rowswz) << 4) + ((k & 7) * 2));
                *(__half*)(sm + OFF_WFR + row * 256 + sw) = __float2half(v);
            }
        }
    }
    // ---- stage XB(0) (GEMM threads; s = 0..255, 6 chunks of 16B each)
    if (!is_scan) {
        int s = tid - 128, t = s >> 3, q = s & 7;
        size_t rowg = ((size_t)bx * L_SEQ + t) * DIM;
        #pragma unroll
        for (int p = 0; p < 6; p++) {
            int cqi = q * 6 + p;
            int arr = cqi >> 4, cc = cqi & 15;
            const char* gp = (arr == 0) ? (const char*)g_xhi
                           : (arr == 1) ? (const char*)g_xlo : (const char*)g_xh;
            uint4 v = *(const uint4*)(gp + (rowg + cc * 8) * 2);
            uint32_t addr = OFF_XB + (uint32_t)(arr * 8192 + t * 256 + ((cc ^ (t & 15)) << 4));
            *(uint4*)(sm + addr) = v;
        }
    }
    // ---- scan init
    const int j = tid;
    float bfv = 0.0f, brv = 0.0f;
    if (is_scan) {
        bfv = bias[nb * 256 + j];
        brv = bias[nb * 256 + 128 + j];
    }
    float c = 0.0f;
    float xt[NT];
    __half fh[NT], rh[NT];
    __syncthreads();

    for (int i = 0; i < NTILES; i++) {
        const int buf = i & 1;
        uint4 pf[6];                             // GEMM-thread prefetch

        if (!is_scan) {
            // -- prefetch x(i+1)
            if (i + 1 < NTILES) {
                int s = tid - 128, t = s >> 3, q = s & 7;
                size_t rowg = ((size_t)bx * L_SEQ + (size_t)(i + 1) * NT + t) * DIM;
                #pragma unroll
                for (int p = 0; p < 6; p++) {
                    int cqi = q * 6 + p;
                    int arr = cqi >> 4, cc = cqi & 15;
                    const char* gp = (arr == 0) ? (const char*)g_xhi
                                   : (arr == 1) ? (const char*)g_xlo : (const char*)g_xh;
                    pf[p] = *(const uint4*)(gp + (rowg + cc * 8) * 2);
                }
            }
            const uint32_t xbb = sb + OFF_XB + (uint32_t)buf * 24576;

            if (wid < 8) {
                // ===== gate-0 warps (u = wid-4): mtiles 2u, 2u+1, 3 combos =====
                const int u = wid - 4;
                float D[2][4][4];
                #pragma unroll
                for (int mi = 0; mi < 2; mi++)
                    #pragma unroll
                    for (int nt = 0; nt < 4; nt++)
                        #pragma unroll
                        for (int e = 0; e < 4; e++) D[mi][nt][e] = 0.0f;

                #pragma unroll
                for (int ks = 0; ks < 8; ks++) {
                    uint32_t Bh[4][2], Bl[4][2];
                    #pragma unroll
                    for (int p = 0; p < 2; p++) {
                        int rp = p * 16 + brow0;
                        uint32_t off = (uint32_t)(rp * 256 + (((2 * ks + bmbit) ^ (rp & 15)) << 4));
                        uint32_t t4[4];
                        ldsm_x4(t4, xbb + off);
                        Bh[2*p][0] = t4[0]; Bh[2*p][1] = t4[1];
                        Bh[2*p+1][0] = t4[2]; Bh[2*p+1][1] = t4[3];
                        ldsm_x4(t4, xbb + 8192 + off);
                        Bl[2*p][0] = t4[0]; Bl[2*p][1] = t4[1];
                        Bl[2*p+1][0] = t4[2]; Bl[2*p+1][1] = t4[3];
                    }
                    #pragma unroll
                    for (int mi = 0; mi < 2; mi++) {
                        int row = (2 * u + mi) * 16 + a_row_add;
                        uint32_t off = (uint32_t)(row * 256 + (((2 * ks + a_chalf) ^ (row & 15)) << 4));
                        uint32_t Axh[4], Axl[4];
                        ldsm_x4(Axh, sb + OFF_WXHI + off);
                        ldsm_x4(Axl, sb + OFF_WXLO + off);
                        #pragma unroll
                        for (int nt = 0; nt < 4; nt++) {
                            mma_bf16(D[mi][nt], Axh, Bh[nt]);
                            mma_bf16(D[mi][nt], Axl, Bh[nt]);
                            mma_bf16(D[mi][nt], Axh, Bl[nt]);
                        }
                    }
                }
                // store U gate0 (fp32)
                float* ux = (float*)(sm + OFF_UX);
                #pragma unroll
                for (int mi = 0; mi < 2; mi++) {
                    int h0 = (2 * u + mi) * 16 + g;
                    #pragma unroll
                    for (int nt = 0; nt < 4; nt++) {
                        int t0 = nt * 8 + tg * 2;
                        ux[(t0)     * DIM + h0]     = D[mi][nt][0];
                        ux[(t0 + 1) * DIM + h0]     = D[mi][nt][1];
                        ux[(t0)     * DIM + h0 + 8] = D[mi][nt][2];
                        ux[(t0 + 1) * DIM + h0 + 8] = D[mi][nt][3];
                    }
                }
            } else {
                // ===== f/r warps (v = wid-8): f mtiles 2v,2v+1 ; r same +128 =====
                const int v = wid - 8;
                float Df[2][4][4], Dr[2][4][4];
                #pragma unroll
                for (int mi = 0; mi < 2; mi++)
                    #pragma unroll
                    for (int nt = 0; nt < 4; nt++)
                        #pragma unroll
                        for (int e = 0; e < 4; e++) { Df[mi][nt][e] = 0.0f; Dr[mi][nt][e] = 0.0f; }

                #pragma unroll
                for (int ks = 0; ks < 8; ks++) {
                    uint32_t Bf[4][2];
                    #pragma unroll
                    for (int p = 0; p < 2; p++) {
                        int rp = p * 16 + brow0;
                        uint32_t off = (uint32_t)(rp * 256 + (((2 * ks + bmbit) ^ (rp & 15)) << 4));
                        uint32_t t4[4];
                        ldsm_x4(t4, xbb + 16384 + off);
                        Bf[2*p][0] = t4[0]; Bf[2*p][1] = t4[1];
                        Bf[2*p+1][0] = t4[2]; Bf[2*p+1][1] = t4[3];
                    }
                    #pragma unroll
                    for (int mi = 0; mi < 2; mi++) {
                        int rowF = (2 * v + mi) * 16 + a_row_add;
                        uint32_t offF = (uint32_t)(rowF * 256 + (((2 * ks + a_chalf) ^ (rowF & 15)) << 4));
                        uint32_t Af[4], Ar[4];
                        ldsm_x4(Af, sb + OFF_WFR + offF);
                        ldsm_x4(Ar, sb + OFF_WFR + 128 * 256 + offF);
                        #pragma unroll
                        for (int nt = 0; nt < 4; nt++) {
                            mma_f16(Df[mi][nt], Af, Bf[nt]);
                            mma_f16(Dr[mi][nt], Ar, Bf[nt]);
                        }
                    }
                }
                // store U f/r (fp16)
                __half* uf = (__half*)(sm + OFF_UF);
                __half* ur = (__half*)(sm + OFF_UR);
                #pragma unroll
                for (int mi = 0; mi < 2; mi++) {
                    int h0 = (2 * v + mi) * 16 + g;
                    #pragma unroll
                    for (int nt = 0; nt < 4; nt++) {
                        int t0 = nt * 8 + tg * 2;
                        uf[(t0)     * DIM + h0]     = __float2half_rn(Df[mi][nt][0]);
                        uf[(t0 + 1) * DIM + h0]     = __float2half_rn(Df[mi][nt][1]);
                        uf[(t0)     * DIM + h0 + 8] = __float2half_rn(Df[mi][nt][2]);
                        uf[(t0 + 1) * DIM + h0 + 8] = __float2half_rn(Df[mi][nt][3]);
                        ur[(t0)     * DIM + h0]     = __float2half_rn(Dr[mi][nt][0]);
                        ur[(t0 + 1) * DIM + h0]     = __float2half_rn(Dr[mi][nt][1]);
                        ur[(t0)     * DIM + h0 + 8] = __float2half_rn(Dr[mi][nt][2]);
                        ur[(t0 + 1) * DIM + h0 + 8] = __float2half_rn(Dr[mi][nt][3]);
                    }
                }
            }
        } else if (i > 0) {
            // ===== scan(i-1), concurrent with GEMM(i); xv from XB[(i-1)&1] =====
            const uint32_t xbb = OFF_XB + (uint32_t)((i - 1) & 1) * 24576;
            float* hp = g_hT + ((size_t)bx * L_SEQ + (size_t)(i - 1) * NT) * DIM + j;
            #pragma unroll
            for (int t = 0; t < NT; t++) {
                float fv = sigf(__half2float(fh[t]) + bfv);
                float rv = sigf(__half2float(rh[t]) + brv);
                c = fmaf(fv, c - xt[t], xt[t]);
                uint32_t xa = xbb + t * 256 + (((j >> 3) ^ (t & 15)) << 4) + ((j & 7) * 2);
                float xv = __bfloat162float(*(__nv_bfloat16*)(sm + xa)) +
                           __bfloat162float(*(__nv_bfloat16*)(sm + xa + 8192));
                hp[t * DIM] = fmaf(rv, c - xv, xv);
            }
        }
        __syncthreads();                         // U(i) visible; scan(i-1) done

        if (!is_scan) {
            // -- STS x(i+1)
            if (i + 1 < NTILES) {
                int s = tid - 128, t = s >> 3, q = s & 7;
                uint32_t bb = OFF_XB + (uint32_t)((i + 1) & 1) * 24576;
                #pragma unroll
                for (int p = 0; p < 6; p++) {
                    int cqi = q * 6 + p;
                    int arr = cqi >> 4, cc = cqi & 15;
                    uint32_t addr = bb + (uint32_t)(arr * 8192 + t * 256 + ((cc ^ (t & 15)) << 4));
                    *(uint4*)(sm + addr) = pf[p];
                }
            }
        } else {
            // -- drain U(i) to registers
            const float*  ux = (const float*)(sm + OFF_UX);
            const __half* uf = (const __half*)(sm + OFF_UF);
            const __half* ur = (const __half*)(sm + OFF_UR);
            #pragma unroll
            for (int t = 0; t < NT; t++) {
                xt[t] = ux[t * DIM + j];
                fh[t] = uf[t * DIM + j];
                rh[t] = ur[t * DIM + j];
            }
        }
        __syncthreads();                         // U free; XB((i+1)&1) staged
    }

    // -- final scan(NTILES-1); XB[1] still intact
    if (is_scan) {
        const uint32_t xbb = OFF_XB + (uint32_t)((NTILES - 1) & 1) * 24576;
        float* hp = g_hT + ((size_t)bx * L_SEQ + (size_t)(NTILES - 1) * NT) * DIM + j;
        #pragma unroll
        for (int t = 0; t < NT; t++) {
            float fv = sigf(__half2float(fh[t]) + bfv);
            float rv = sigf(__half2float(rh[t]) + brv);
            c = fmaf(fv, c - xt[t], xt[t]);
            uint32_t xa = xbb + t * 256 + (((j >> 3) ^ (t & 15)) << 4) + ((j & 7) * 2);
            float xv = __bfloat162float(*(__nv_bfloat16*)(sm + xa)) +
                       __bfloat162float(*(__nv_bfloat16*)(sm + xa + 8192));
            hp[t * DIM] = fmaf(rv, c - xv, xv);
        }
    }
}

extern "C" void kernel_launch(void* const* d_in, const int* in_sizes, int n_in,
                              void* d_out, int out_size) {
    const float* x  = (const float*)d_in[0];
    const float* W  = (const float*)d_in[1];
    const float* bi = (const float*)d_in[2];
    float* out = (float*)d_out;

    transpose_x<<<(L_SEQ / TP_T) * BATCH, 256>>>(x);
    cudaFuncSetAttribute(sru_main, cudaFuncAttributeMaxDynamicSharedMemorySize, SMEM_MAIN);
    sru_main<<<BATCH * NBI, 384, SMEM_MAIN>>>(W, bi);
    untranspose_h<<<(L_SEQ / TP_T) * BATCH, 256>>>(out);
}

// round 14
// speedup vs baseline: 1.4313x; 1.2760x over previous
#include <cuda_runtime.h>
#include <cuda_bf16.h>
#include <cuda_fp16.h>
#include <cstdint>

// BatchSRU: L=2048, B=8, D=128, NB=16, fp32.
// x_tilde: 3-combo bf16 hi/lo HMMA; f,r: single fp16 HMMA (validated ~1.5e-4).
// R10 skeleton: NT=16, 384 threads; warps 4-11 GEMM (each: 1 x_tilde mtile
// 3-combo + 1 f + 1 r mtile fp16), warps 0-3 scan tile i-1 concurrently.
// Pass1: transpose+split -> g_xhi/g_xlo (bf16) + g_xh (fp16).
// Pass3: untranspose g_hT -> out.

#define L_SEQ 2048
#define BATCH 8
#define DIM   128
#define NBI   16
#define NT    16
#define NTILES 128

__device__ __nv_bfloat16 g_xhi[BATCH * NBI * L_SEQ * DIM];
__device__ __nv_bfloat16 g_xlo[BATCH * NBI * L_SEQ * DIM];
__device__ __half        g_xh [BATCH * NBI * L_SEQ * DIM];
__device__ float         g_hT [BATCH * NBI * L_SEQ * DIM];

// SMEM: W resident 128K + XB 2x12K + U 16K = 172K
#define OFF_WXHI 0            // 128 rows x 256 B
#define OFF_WXLO 32768
#define OFF_WF   65536        // fp16 f-gate W
#define OFF_WR2  98304        // fp16 r-gate W
#define OFF_XB   131072       // 2 bufs x 12288: [xhi 4096][xlo 4096][xh 4096]
#define OFF_UX   155648       // fp32 [16][128]
#define OFF_UF   163840       // fp16 [16][128]
#define OFF_UR   167936       // fp16 [16][128]
#define SMEM_MAIN 172032

__device__ __forceinline__ uint32_t smem_u32(const void* p) {
    uint32_t a;
    asm("{ .reg .u64 t; cvta.to.shared.u64 t, %1; cvt.u32.u64 %0, t; }" : "=r"(a) : "l"(p));
    return a;
}
__device__ __forceinline__ void ldsm_x4(uint32_t* r, uint32_t addr) {
    asm volatile("ldmatrix.sync.aligned.m8n8.x4.shared.b16 {%0,%1,%2,%3}, [%4];"
                 : "=r"(r[0]), "=r"(r[1]), "=r"(r[2]), "=r"(r[3]) : "r"(addr));
}
__device__ __forceinline__ void ldsm_x2(uint32_t* r, uint32_t addr) {
    asm volatile("ldmatrix.sync.aligned.m8n8.x2.shared.b16 {%0,%1}, [%2];"
                 : "=r"(r[0]), "=r"(r[1]) : "r"(addr));
}
__device__ __forceinline__ void mma_bf16(float* d, const uint32_t* a, const uint32_t* b) {
    asm volatile("mma.sync.aligned.m16n8k16.row.col.f32.bf16.bf16.f32 "
                 "{%0,%1,%2,%3}, {%4,%5,%6,%7}, {%8,%9}, {%0,%1,%2,%3};"
                 : "+f"(d[0]), "+f"(d[1]), "+f"(d[2]), "+f"(d[3])
                 : "r"(a[0]), "r"(a[1]), "r"(a[2]), "r"(a[3]), "r"(b[0]), "r"(b[1]));
}
__device__ __forceinline__ void mma_f16(float* d, const uint32_t* a, const uint32_t* b) {
    asm volatile("mma.sync.aligned.m16n8k16.row.col.f32.f16.f16.f32 "
                 "{%0,%1,%2,%3}, {%4,%5,%6,%7}, {%8,%9}, {%0,%1,%2,%3};"
                 : "+f"(d[0]), "+f"(d[1]), "+f"(d[2]), "+f"(d[3])
                 : "r"(a[0]), "r"(a[1]), "r"(a[2]), "r"(a[3]), "r"(b[0]), "r"(b[1]));
}
__device__ __forceinline__ float sigf(float z) {
    return __fdividef(1.0f, 1.0f + __expf(-z));
}

// ============ Pass 1: transpose + bf16 split + fp16 copy ============
#define TP_T 4
__global__ void __launch_bounds__(256) transpose_x(const float* __restrict__ x) {
    __shared__ float sm[TP_T * 16 * 129];
    const int bx = blockIdx.x;
    const int t0 = (bx >> 3) * TP_T;
    const int b  = bx & 7;
    #pragma unroll 4
    for (int i = 0; i < 32; i++) {
        int idx  = i * 256 + threadIdx.x;
        int tloc = idx >> 11;
        int rem  = idx & 2047;                  // k*16 + nb
        float v = x[((size_t)(t0 + tloc) * BATCH + b) * 2048 + rem];
        sm[(tloc * 16 + (rem & 15)) * 129 + (rem >> 4)] = v;
    }
    __syncthreads();
    #pragma unroll 4
    for (int i = 0; i < 32; i++) {
        int idx = i * 256 + threadIdx.x;
        int k = idx & 127;
        int chunk = idx >> 7;                   // nb*4 + tloc
        int nb = chunk >> 2, tloc = chunk & 3;
        float v = sm[(tloc * 16 + nb) * 129 + k];
        __nv_bfloat16 hi = __float2bfloat16(v);
        __nv_bfloat16 lo = __float2bfloat16(v - __bfloat162float(hi));
        size_t o = ((size_t)(b * NBI + nb) * L_SEQ + t0 + tloc) * DIM + k;
        g_xhi[o] = hi;
        g_xlo[o] = lo;
        g_xh[o]  = __float2half(v);
    }
}

// ============ Pass 3: untranspose h ============
__global__ void __launch_bounds__(256) untranspose_h(float* __restrict__ out) {
    __shared__ float sm[TP_T * 16 * 129];
    const int bx = blockIdx.x;
    const int t0 = (bx >> 3) * TP_T;
    const int b  = bx & 7;
    #pragma unroll 4
    for (int i = 0; i < 32; i++) {
        int idx = i * 256 + threadIdx.x;
        int k = idx & 127;
        int chunk = idx >> 7;
        int nb = chunk >> 2, tloc = chunk & 3;
        sm[(tloc * 16 + nb) * 129 + k] =
            g_hT[((size_t)(b * NBI + nb) * L_SEQ + t0 + tloc) * DIM + k];
    }
    __syncthreads();
    #pragma unroll 4
    for (int i = 0; i < 32; i++) {
        int idx  = i * 256 + threadIdx.x;
        int tloc = idx >> 11;
        int rem  = idx & 2047;
        out[((size_t)(t0 + tloc) * BATCH + b) * 2048 + rem] =
            sm[(tloc * 16 + (rem & 15)) * 129 + (rem >> 4)];
    }
}

// ============ Pass 2: main (384 threads) ============
__global__ void __launch_bounds__(384, 1) sru_main(
    const float* __restrict__ W, const float* __restrict__ bias)
{
    extern __shared__ char sm[];
    const uint32_t sb = smem_u32(sm);
    const int tid  = threadIdx.x;
    const int lane = tid & 31;
    const int wid  = tid >> 5;
    const int bx = blockIdx.x, nb = bx & 15;
    const bool is_scan = (tid < 128);

    // lane constants
    const int a_tile    = lane >> 3;
    const int a_row_add = (lane & 7) + ((a_tile & 1) << 3);
    const int a_chalf   = a_tile >> 1;
    const int b_row     = lane & 7;
    const int b_chalf   = (lane >> 3) & 1;
    const int g  = lane >> 2;
    const int tg = lane & 3;
    const int wg = wid - 4;                      // GEMM warp 0..7

    // ---- startup: stage W (thread owns column h = tid, 0..383)
    {
        const float* Wp = W + (size_t)nb * (DIM * 3 * DIM);
        const int h = tid;
        const int lr = h & 127;                  // local row in its region
        const uint32_t rowswz = (uint32_t)(lr & 15);
        if (h < 128) {
            #pragma unroll 4
            for (int k = 0; k < 128; k++) {
                float v = Wp[k * 384 + h];
                __nv_bfloat16 hi = __float2bfloat16(v);
                __nv_bfloat16 lo = __float2bfloat16(v - __bfloat162float(hi));
                uint32_t sw = (uint32_t)((((k >> 3) ^ rowswz) << 4) + ((k & 7) * 2));
                *(__nv_bfloat16*)(sm + OFF_WXHI + lr * 256 + sw) = hi;
                *(__nv_bfloat16*)(sm + OFF_WXLO + lr * 256 + sw) = lo;
            }
        } else {
            const uint32_t base = (h < 256) ? OFF_WF : OFF_WR2;
            #pragma unroll 4
            for (int k = 0; k < 128; k++) {
                float v = Wp[k * 384 + h];
                uint32_t sw = (uint32_t)((((k >> 3) ^ rowswz) << 4) + ((k & 7) * 2));
                *(__half*)(sm + base + lr * 256 + sw) = __float2half(v);
            }
        }
    }
    // ---- scan init + stage XB(0)
    const int j = tid;                           // channel (scan threads)
    float bfv = 0.0f, brv = 0.0f;
    if (is_scan) {
        bfv = bias[nb * 256 + j];
        brv = bias[nb * 256 + 128 + j];
        int t = tid >> 3, q = tid & 7, cc = q * 2;
        size_t o = ((size_t)bx * L_SEQ + t) * DIM + q * 16;
        uint4 H0 = *(const uint4*)(g_xhi + o), H1 = *(const uint4*)(g_xhi + o + 8);
        uint4 L0 = *(const uint4*)(g_xlo + o), L1 = *(const uint4*)(g_xlo + o + 8);
        uint4 F0 = *(const uint4*)(g_xh + o),  F1 = *(const uint4*)(g_xh + o + 8);
        uint32_t base = OFF_XB + (uint32_t)t * 256;
        *(uint4*)(sm + base + ((cc ^ t) << 4))       = H0;
        *(uint4*)(sm + base + (((cc + 1) ^ t) << 4)) = H1;
        *(uint4*)(sm + base + 4096 + ((cc ^ t) << 4))       = L0;
        *(uint4*)(sm + base + 4096 + (((cc + 1) ^ t) << 4)) = L1;
        *(uint4*)(sm + base + 8192 + ((cc ^ t) << 4))       = F0;
        *(uint4*)(sm + base + 8192 + (((cc + 1) ^ t) << 4)) = F1;
    }
    float c = 0.0f;
    float xt[NT], xv[NT];
    __half fh[NT], rh[NT];
    __syncthreads();

    for (int i = 0; i < NTILES; i++) {
        const int buf = i & 1;
        uint4 H0, H1, L0, L1, F0, F1;            // scan-thread prefetch regs

        if (!is_scan) {
            // ---------- GEMM(i): warp wg owns x~-mtile wg, f-mtile wg, r-mtile wg
            float Dx[2][4], Df[2][4], Dr[2][4];
            #pragma unroll
            for (int nt = 0; nt < 2; nt++)
                #pragma unroll
                for (int e = 0; e < 4; e++) { Dx[nt][e] = 0.0f; Df[nt][e] = 0.0f; Dr[nt][e] = 0.0f; }

            const uint32_t xb = sb + OFF_XB + (uint32_t)buf * 12288;
            const int arow = wg * 16 + a_row_add;          // 0..127
            #pragma unroll
            for (int ks = 0; ks < 8; ks++) {
                uint32_t Bhi[2][2], Blo[2][2], Bf[2][2];
                #pragma unroll
                for (int nt = 0; nt < 2; nt++) {
                    int trow = nt * 8 + b_row;
                    uint32_t ba = xb + trow * 256 + (((2 * ks + b_chalf) ^ trow) << 4);
                    ldsm_x2(Bhi[nt], ba);
                    ldsm_x2(Blo[nt], ba + 4096);
                    ldsm_x2(Bf[nt],  ba + 8192);
                }
                uint32_t aoff = (uint32_t)(arow * 256 + (((2 * ks + a_chalf) ^ (arow & 15)) << 4));
                uint32_t Axh[4], Axl[4], Af[4], Ar[4];
                ldsm_x4(Axh, sb + OFF_WXHI + aoff);
                ldsm_x4(Axl, sb + OFF_WXLO + aoff);
                ldsm_x4(Af,  sb + OFF_WF   + aoff);
                ldsm_x4(Ar,  sb + OFF_WR2  + aoff);
                #pragma unroll
                for (int nt = 0; nt < 2; nt++) {
                    mma_bf16(Dx[nt], Axh, Bhi[nt]);
                    mma_bf16(Dx[nt], Axl, Bhi[nt]);
                    mma_bf16(Dx[nt], Axh, Blo[nt]);
                    mma_f16(Df[nt], Af, Bf[nt]);
                    mma_f16(Dr[nt], Ar, Bf[nt]);
                }
            }
            // -- store U(i): channel rows h0 = wg*16 + ...
            {
                int h0 = wg * 16 + g;
                float*  ux = (float*)(sm + OFF_UX);
                __half* uf = (__half*)(sm + OFF_UF);
                __half* ur = (__half*)(sm + OFF_UR);
                #pragma unroll
                for (int nt = 0; nt < 2; nt++) {
                    int t0 = nt * 8 + tg * 2;
                    ux[(t0)     * DIM + h0]     = Dx[nt][0];
                    ux[(t0 + 1) * DIM + h0]     = Dx[nt][1];
                    ux[(t0)     * DIM + h0 + 8] = Dx[nt][2];
                    ux[(t0 + 1) * DIM + h0 + 8] = Dx[nt][3];
                    uf[(t0)     * DIM + h0]     = __float2half_rn(Df[nt][0]);
                    uf[(t0 + 1) * DIM + h0]     = __float2half_rn(Df[nt][1]);
                    uf[(t0)     * DIM + h0 + 8] = __float2half_rn(Df[nt][2]);
                    uf[(t0 + 1) * DIM + h0 + 8] = __float2half_rn(Df[nt][3]);
                    ur[(t0)     * DIM + h0]     = __float2half_rn(Dr[nt][0]);
                    ur[(t0 + 1) * DIM + h0]     = __float2half_rn(Dr[nt][1]);
                    ur[(t0)     * DIM + h0 + 8] = __float2half_rn(Dr[nt][2]);
                    ur[(t0 + 1) * DIM + h0 + 8] = __float2half_rn(Dr[nt][3]);
                }
            }
        } else {
            // ---------- scan(i-1) + LDG prefetch x(i+1), concurrent with GEMM(i)
            if (i + 1 < NTILES) {
                int t = tid >> 3, q = tid & 7;
                size_t o = ((size_t)bx * L_SEQ + (size_t)(i + 1) * NT + t) * DIM + q * 16;
                H0 = *(const uint4*)(g_xhi + o); H1 = *(const uint4*)(g_xhi + o + 8);
                L0 = *(const uint4*)(g_xlo + o); L1 = *(const uint4*)(g_xlo + o + 8);
                F0 = *(const uint4*)(g_xh + o);  F1 = *(const uint4*)(g_xh + o + 8);
            }
            if (i > 0) {
                float* hp = g_hT + ((size_t)bx * L_SEQ + (size_t)(i - 1) * NT) * DIM + j;
                #pragma unroll
                for (int t = 0; t < NT; t++) {
                    float fv = sigf(__half2float(fh[t]) + bfv);
                    float rv = sigf(__half2float(rh[t]) + brv);
                    c = fmaf(fv, c - xt[t], xt[t]);
                    hp[t * DIM] = fmaf(rv, c - xv[t], xv[t]);
                }
            }
        }
        __syncthreads();                         // U(i) visible; scan(i-1) done

        if (is_scan) {
            // -- stage XB(i+1)
            if (i + 1 < NTILES) {
                int t = tid >> 3, q = tid & 7, cc = q * 2;
                uint32_t base = OFF_XB + (uint32_t)((i + 1) & 1) * 12288 + (uint32_t)t * 256;
                *(uint4*)(sm + base + ((cc ^ t) << 4))       = H0;
                *(uint4*)(sm + base + (((cc + 1) ^ t) << 4)) = H1;
                *(uint4*)(sm + base + 4096 + ((cc ^ t) << 4))       = L0;
                *(uint4*)(sm + base + 4096 + (((cc + 1) ^ t) << 4)) = L1;
                *(uint4*)(sm + base + 8192 + ((cc ^ t) << 4))       = F0;
                *(uint4*)(sm + base + 8192 + (((cc + 1) ^ t) << 4)) = F1;
            }
            // -- drain U(i) and xv(i) into registers
            const float*  ux = (const float*)(sm + OFF_UX);
            const __half* uf = (const __half*)(sm + OFF_UF);
            const __half* ur = (const __half*)(sm + OFF_UR);
            const uint32_t xbb = OFF_XB + (uint32_t)buf * 12288;
            #pragma unroll
            for (int t = 0; t < NT; t++) {
                xt[t] = ux[t * DIM + j];
                fh[t] = uf[t * DIM + j];
                rh[t] = ur[t * DIM + j];
                uint32_t xa = xbb + t * 256 + (((j >> 3) ^ t) << 4) + ((j & 7) * 2);
                xv[t] = __bfloat162float(*(__nv_bfloat16*)(sm + xa)) +
                        __bfloat162float(*(__nv_bfloat16*)(sm + xa + 4096));
            }
        }
        __syncthreads();                         // U free; XB((i+1)&1) staged
    }

    // -- final scan(NTILES-1)
    if (is_scan) {
        float* hp = g_hT + ((size_t)bx * L_SEQ + (size_t)(NTILES - 1) * NT) * DIM + j;
        #pragma unroll
        for (int t = 0; t < NT; t++) {
            float fv = sigf(__half2float(fh[t]) + bfv);
            float rv = sigf(__half2float(rh[t]) + brv);
            c = fmaf(fv, c - xt[t], xt[t]);
            hp[t * DIM] = fmaf(rv, c - xv[t], xv[t]);
        }
    }
}

extern "C" void kernel_launch(void* const* d_in, const int* in_sizes, int n_in,
                              void* d_out, int out_size) {
    const float* x  = (const float*)d_in[0];
    const float* W  = (const float*)d_in[1];
    const float* bi = (const float*)d_in[2];
    float* out = (float*)d_out;

    transpose_x<<<(L_SEQ / TP_T) * BATCH, 256>>>(x);
    cudaFuncSetAttribute(sru_main, cudaFuncAttributeMaxDynamicSharedMemorySize, SMEM_MAIN);
    sru_main<<<BATCH * NBI, 384, SMEM_MAIN>>>(W, bi);
    untranspose_h<<<(L_SEQ / TP_T) * BATCH, 256>>>(out);
}